// round 15
// baseline (speedup 1.0000x reference)
#include <cuda_runtime.h>
#include <cstdint>

#define N 8192
#define F 128
#define ALPHA 0.2f
#define PRO_BLOCKS 148
#define PRO_WARPS (PRO_BLOCKS * 32)

// Allocation-free scratch
__device__ float    g_si[N];
__device__ float    g_sj[N];
__device__ float    g_sum[N];
__device__ uint32_t g_mask[N * 256];   // 8 MB: 1 bit/element, K2 access order

// Prologue (frozen R9/R12): one wave, early vi/vj loads, coalesced Wa.
__global__ __launch_bounds__(1024) void prologue_kernel(
    const float* __restrict__ vi, const float* __restrict__ vj,
    const float* __restrict__ W, const float* __restrict__ a) {
#if __CUDA_ARCH__ >= 900
    cudaTriggerProgrammaticLaunchCompletion();
#endif
    __shared__ float sWa1[F];
    __shared__ float sWa2[F];

    const int tid = threadIdx.x;
    const int lane = tid & 31;
    const int wid = tid >> 5;

    const int row0 = blockIdx.x * 32 + wid;
    const int row1 = row0 + PRO_WARPS;
    const bool has1 = (row1 < N);
    float4 x1a = reinterpret_cast<const float4*>(vi + (size_t)row0 * F)[lane];
    float4 x2a = reinterpret_cast<const float4*>(vj + (size_t)row0 * F)[lane];
    float4 x1b = make_float4(0.f, 0.f, 0.f, 0.f);
    float4 x2b = make_float4(0.f, 0.f, 0.f, 0.f);
    if (has1) {
        x1b = reinterpret_cast<const float4*>(vi + (size_t)row1 * F)[lane];
        x2b = reinterpret_cast<const float4*>(vj + (size_t)row1 * F)[lane];
    }

    const float4 a1v = reinterpret_cast<const float4*>(a)[lane];
    const float4 a2v = reinterpret_cast<const float4*>(a)[32 + lane];

#pragma unroll
    for (int r = 0; r < 4; ++r) {
        const int row = wid * 4 + r;
        float4 wv = reinterpret_cast<const float4*>(W + row * F)[lane];
        float s1 = fmaf(wv.x, a1v.x, fmaf(wv.y, a1v.y, fmaf(wv.z, a1v.z, wv.w * a1v.w)));
        float s2 = fmaf(wv.x, a2v.x, fmaf(wv.y, a2v.y, fmaf(wv.z, a2v.z, wv.w * a2v.w)));
#pragma unroll
        for (int o = 16; o > 0; o >>= 1) {
            s1 += __shfl_xor_sync(0xffffffffu, s1, o);
            s2 += __shfl_xor_sync(0xffffffffu, s2, o);
        }
        if (lane == 0) { sWa1[row] = s1; sWa2[row] = s2; }
    }
    __syncthreads();

    const float4 a1 = reinterpret_cast<const float4*>(sWa1)[lane];
    const float4 a2 = reinterpret_cast<const float4*>(sWa2)[lane];
    {
        float s1 = fmaf(x1a.x, a1.x, fmaf(x1a.y, a1.y, fmaf(x1a.z, a1.z, x1a.w * a1.w)));
        float s2 = fmaf(x2a.x, a2.x, fmaf(x2a.y, a2.y, fmaf(x2a.z, a2.z, x2a.w * a2.w)));
#pragma unroll
        for (int o = 16; o > 0; o >>= 1) {
            s1 += __shfl_down_sync(0xffffffffu, s1, o);
            s2 += __shfl_down_sync(0xffffffffu, s2, o);
        }
        if (lane == 0) { g_si[row0] = s1; g_sj[row0] = s2; }
    }
    if (has1) {
        float s1 = fmaf(x1b.x, a1.x, fmaf(x1b.y, a1.y, fmaf(x1b.z, a1.z, x1b.w * a1.w)));
        float s2 = fmaf(x2b.x, a2.x, fmaf(x2b.y, a2.y, fmaf(x2b.z, a2.z, x2b.w * a2.w)));
#pragma unroll
        for (int o = 16; o > 0; o >>= 1) {
            s1 += __shfl_down_sync(0xffffffffu, s1, o);
            s2 += __shfl_down_sync(0xffffffffu, s2, o);
        }
        if (lane == 0) { g_si[row1] = s1; g_sj[row1] = s2; }
    }
}

// K1: read-dominated. adj row -> masked-exp sum + packed 1-bit mask in
// K2's per-thread order: g_mask[row*256+tid] bit (it*4+c) = mask of element
// (tid + it*256)*4 + c.
__global__ __launch_bounds__(256, 8) void mask_sum_kernel(
    const int* __restrict__ adj) {
    __shared__ float red[8];

    const int row = blockIdx.x;
    const int tid = threadIdx.x;
    const int lane = tid & 31;
    const int wid = tid >> 5;

    const int4*   adj4 = reinterpret_cast<const int4*>(adj + (size_t)row * N);
    const float4* sj4  = reinterpret_cast<const float4*>(g_sj);

    if (row < 2368) {
#pragma unroll
        for (int it = 0; it < 8; ++it)
            asm volatile("prefetch.global.L2 [%0];" :: "l"(adj4 + tid + it * 256));
    }
#if __CUDA_ARCH__ >= 900
    cudaGridDependencySynchronize();
#endif

    const float si = g_si[row];
    uint32_t mword = 0;
    float lsum = 0.f;
#pragma unroll
    for (int it = 0; it < 8; ++it) {
        const int j = tid + it * 256;
        int4   av = __ldcs(&adj4[j]);
        float4 sj = sj4[j];
        float t, p;
        t = si + sj.x; t = t > 0.f ? t : ALPHA * t; p = av.x > 0 ? __expf(t) : 0.f;
        lsum += p; mword |= (av.x > 0 ? 1u : 0u) << (it * 4 + 0);
        t = si + sj.y; t = t > 0.f ? t : ALPHA * t; p = av.y > 0 ? __expf(t) : 0.f;
        lsum += p; mword |= (av.y > 0 ? 1u : 0u) << (it * 4 + 1);
        t = si + sj.z; t = t > 0.f ? t : ALPHA * t; p = av.z > 0 ? __expf(t) : 0.f;
        lsum += p; mword |= (av.z > 0 ? 1u : 0u) << (it * 4 + 2);
        t = si + sj.w; t = t > 0.f ? t : ALPHA * t; p = av.w > 0 ? __expf(t) : 0.f;
        lsum += p; mword |= (av.w > 0 ? 1u : 0u) << (it * 4 + 3);
    }
    g_mask[row * 256 + tid] = mword;           // coalesced 1 KB/row

#pragma unroll
    for (int o = 16; o > 0; o >>= 1)
        lsum += __shfl_xor_sync(0xffffffffu, lsum, o);
    if (lane == 0) red[wid] = lsum;
    __syncthreads();
    if (wid == 0) {
        float s = (lane < 8) ? red[lane] : 0.f;
#pragma unroll
        for (int o = 4; o > 0; o >>= 1)
            s += __shfl_xor_sync(0xffffffffu, s, o);
        if (lane == 0) g_sum[row] = s;
    }
}

// K2: write-dominated. Recompute exp (deterministic), scale by 1/sum, stream
// out. No staging, no reduction; mask (8MB) comes from L2.
__global__ __launch_bounds__(256, 8) void scale_write_kernel(
    float* __restrict__ out) {
#if __CUDA_ARCH__ >= 900
    cudaGridDependencySynchronize();
#endif
    const int row = blockIdx.x;
    const int tid = threadIdx.x;

    const float4* sj4 = reinterpret_cast<const float4*>(g_sj);
    float4* out4 = reinterpret_cast<float4*>(out + (size_t)row * N);

    const float si  = g_si[row];
    const float inv = 1.0f / g_sum[row];
    const uint32_t mword = g_mask[row * 256 + tid];

#pragma unroll
    for (int it = 0; it < 8; ++it) {
        const int j = tid + it * 256;
        float4 sj = sj4[j];
        float4 p;
        float t;
        t = si + sj.x; t = t > 0.f ? t : ALPHA * t;
        p.x = (mword >> (it * 4 + 0)) & 1u ? __expf(t) * inv : 0.f;
        t = si + sj.y; t = t > 0.f ? t : ALPHA * t;
        p.y = (mword >> (it * 4 + 1)) & 1u ? __expf(t) * inv : 0.f;
        t = si + sj.z; t = t > 0.f ? t : ALPHA * t;
        p.z = (mword >> (it * 4 + 2)) & 1u ? __expf(t) * inv : 0.f;
        t = si + sj.w; t = t > 0.f ? t : ALPHA * t;
        p.w = (mword >> (it * 4 + 3)) & 1u ? __expf(t) * inv : 0.f;
        __stcs(&out4[j], p);
    }
}

extern "C" void kernel_launch(void* const* d_in, const int* in_sizes, int n_in,
                              void* d_out, int out_size) {
    const float* v_i = (const float*)d_in[0];
    const float* v_j = (const float*)d_in[1];
    const int*   adj = (const int*)d_in[2];
    const float* W   = (const float*)d_in[3];
    const float* a   = (const float*)d_in[4];
    float* out = (float*)d_out;

    prologue_kernel<<<PRO_BLOCKS, 1024>>>(v_i, v_j, W, a);

    cudaLaunchAttribute attrs[1];
    attrs[0].id = cudaLaunchAttributeProgrammaticStreamSerialization;
    attrs[0].val.programmaticStreamSerializationAllowed = 1;

    cudaLaunchConfig_t cfg1 = {};
    cfg1.gridDim = dim3(N, 1, 1);
    cfg1.blockDim = dim3(256, 1, 1);
    cfg1.stream = 0;
    cfg1.attrs = attrs;
    cfg1.numAttrs = 1;
    cudaLaunchKernelEx(&cfg1, mask_sum_kernel, adj);

    cudaLaunchConfig_t cfg2 = {};
    cfg2.gridDim = dim3(N, 1, 1);
    cfg2.blockDim = dim3(256, 1, 1);
    cfg2.stream = 0;
    cfg2.attrs = attrs;
    cfg2.numAttrs = 1;
    cudaLaunchKernelEx(&cfg2, scale_write_kernel, out);
}